// round 16
// baseline (speedup 1.0000x reference)
#include <cuda_runtime.h>
#include <cuda_fp16.h>
#include <cuda_bf16.h>
#include <cstdint>

static constexpr int CCH = 64;
static constexpr int HH  = 480;
static constexpr int WW  = 640;
static constexpr long long HWSZ = (long long)HH * WW;   // 307200
static constexpr long long NV   = 256LL * 256 * 32;     // 2097152 voxels
static constexpr int TILE = 256;                        // voxels per block (2 halves)
static constexpr int HALF = 128;
static constexpr int PITCH_H = 66;                      // halves per smem row (132B)
static constexpr int PITCH_W = 33;                      // 32-bit words per row

// Scratch: transposed fp16 features, xTh[pixel * 64 + channel]  (39 MB, L2-resident)
__device__ __align__(16) __half g_xTh[(size_t)HWSZ * CCH];

// ---------------------------------------------------------------------------
// Transpose x2d (C, H*W) f32 -> xTh (H*W, C) f16.
// float4 streaming loads (read-once, keep L2 for xT), smem tile, half2 writes.
// ---------------------------------------------------------------------------
__global__ void __launch_bounds__(256) k_transpose(const float* __restrict__ x2d)
{
    __shared__ float tile[64][65];        // tile[channel][pixel]
    const int pbase = blockIdx.x * 64;
    const int tid  = threadIdx.x;
    const int c    = tid >> 2;            // 0..63 : channel
    const int q    = tid & 3;             // 0..3  : float4 quarter
    const int lane = tid & 31;
    const int w    = tid >> 5;            // 0..7

    const float4* src = reinterpret_cast<const float4*>(x2d + (long long)c * HWSZ + pbase);
#pragma unroll
    for (int it = 0; it < 4; it++) {
        const float4 v = __ldcs(src + q + it * 4);   // streaming: read-once
        const int p0 = (q + it * 4) * 4;
        tile[c][p0 + 0] = v.x;
        tile[c][p0 + 1] = v.y;
        tile[c][p0 + 2] = v.z;
        tile[c][p0 + 3] = v.w;
    }
    __syncthreads();

    __half2* xT2 = reinterpret_cast<__half2*>(g_xTh);
#pragma unroll
    for (int it = 0; it < 8; it++) {
        const int p  = it * 8 + w;
        const int c2 = lane * 2;
        const __half2 h = __floats2half2_rn(tile[c2][p], tile[c2 + 1][p]);
        xT2[(long long)(pbase + p) * 32 + lane] = h;
    }
}

__device__ __forceinline__ void sts_row(uint32_t* su, int v, int kk, const uint4& r)
{
    const int wbase = v * PITCH_W + 4 * kk;   // scalar STS.32 x4: conflict-free
    su[wbase + 0] = r.x;
    su[wbase + 1] = r.y;
    su[wbase + 2] = r.z;
    su[wbase + 3] = r.w;
}

// ---------------------------------------------------------------------------
// Fused kernel (512 threads, occ ~97%), 2-half pipeline:
//   A; bar; Bload(0); Bstore(0); bar; Bload(1); C(0); Bstore(1); bar; C(1)
// Output stores are write-through (__stwt): the 512 MB stream bypasses L2
// dirty-line allocate/evict and never pressures xT's residency.
// ---------------------------------------------------------------------------
__global__ void __launch_bounds__(512) k_fuse(
    const int*   __restrict__ ppix,     // (N, 2) int32 : x, y
    const int*   __restrict__ scale_p,  // scalar int32
    const int*   __restrict__ mask,     // (N,) int32 (bool)
    const float* __restrict__ pz,       // (N,) float32
    const float* __restrict__ depth,    // (H*W,) float32
    float*       __restrict__ out)      // (64, N) float32
{
    __shared__ __align__(16) __half sm16[TILE][PITCH_H];  // 2 halves of 128 rows
    __shared__ float sm_w[TILE];
    __shared__ int   sm_fidx[TILE];

    uint32_t* su = reinterpret_cast<uint32_t*>(&sm16[0][0]);
    const int tid = threadIdx.x;
    const long long vbase = (long long)blockIdx.x * TILE;

    // ---- Phase A: indices + weights (threads 0..255, one voxel each) ----
    if (tid < TILE) {
        const long long i = vbase + tid;
        const int2 p = reinterpret_cast<const int2*>(ppix)[i];
        const int  m = mask[i];
        const float z = pz[i];
        const int scale = scale_p[0];
        const int di = p.y * WW + p.x;
        const int fi = (scale == 1) ? di : ((p.y / scale) * WW + (p.x / scale));
        sm_fidx[tid] = fi;
        const float dv = m ? __ldg(depth + di) : 0.0f;
        const float d  = z - dv;
        const float gw = __expf(-0.5f * d * d);   // sigma = 1
        sm_w[tid] = m ? ((dv == 0.0f) ? 1.0f : gw) : 0.0f;
    }
    __syncthreads();

    // Gather lane mapping: 8 lanes per 128B fp16 voxel row.
    const int vt = tid >> 3;        // 0..63: voxel slot within pass
    const int kk = tid & 7;         // 0..7 : 16B chunk within row

    uint4 r0, r1;

    // ---- B_load(0) + B_store(0): rows 0..127 ----
    {
        const int va = vt;
        const int vb = 64 + vt;
        r0 = make_uint4(0u, 0u, 0u, 0u);
        r1 = make_uint4(0u, 0u, 0u, 0u);
        if (sm_w[va] != 0.0f)
            r0 = __ldg(reinterpret_cast<const uint4*>(g_xTh + (long long)sm_fidx[va] * CCH) + kk);
        if (sm_w[vb] != 0.0f)
            r1 = __ldg(reinterpret_cast<const uint4*>(g_xTh + (long long)sm_fidx[vb] * CCH) + kk);
        sts_row(su, va, kk, r0);
        sts_row(su, vb, kk, r1);
    }
    __syncthreads();

    // ---- B_load(1): rows 128..255 (latency overlapped with C(0)) ----
    {
        const int va = HALF + vt;
        const int vb = HALF + 64 + vt;
        r0 = make_uint4(0u, 0u, 0u, 0u);
        r1 = make_uint4(0u, 0u, 0u, 0u);
        if (sm_w[va] != 0.0f)
            r0 = __ldg(reinterpret_cast<const uint4*>(g_xTh + (long long)sm_fidx[va] * CCH) + kk);
        if (sm_w[vb] != 0.0f)
            r1 = __ldg(reinterpret_cast<const uint4*>(g_xTh + (long long)sm_fidx[vb] * CCH) + kk);
    }

    // ---- C(0): store half 0 while half-1 gather is in flight ----
    {
        const int vv = tid & (HALF - 1);       // 0..127
        const int cq = tid >> 7;               // 0..3: 16-channel quarter
        const float wv = sm_w[vv];
        float* op = out + vbase + vv;
        const int wrow = vv * PITCH_W;
#pragma unroll
        for (int it = 0; it < 8; it++) {
            const int c = cq * 16 + it * 2;
            const uint32_t bits = su[wrow + (c >> 1)];
            const float2 f = __half22float2(*reinterpret_cast<const __half2*>(&bits));
            __stwt(op + (long long)c * NV,       f.x * wv);
            __stwt(op + (long long)(c + 1) * NV, f.y * wv);
        }
    }

    // ---- B_store(1) ----
    sts_row(su, HALF + vt, kk, r0);
    sts_row(su, HALF + 64 + vt, kk, r1);
    __syncthreads();

    // ---- C(1): store half 1 ----
    {
        const int vv = tid & (HALF - 1);
        const int cq = tid >> 7;
        const int row = HALF + vv;
        const float wv = sm_w[row];
        float* op = out + vbase + row;
        const int wrow = row * PITCH_W;
#pragma unroll
        for (int it = 0; it < 8; it++) {
            const int c = cq * 16 + it * 2;
            const uint32_t bits = su[wrow + (c >> 1)];
            const float2 f = __half22float2(*reinterpret_cast<const __half2*>(&bits));
            __stwt(op + (long long)c * NV,       f.x * wv);
            __stwt(op + (long long)(c + 1) * NV, f.y * wv);
        }
    }
}

extern "C" void kernel_launch(void* const* d_in, const int* in_sizes, int n_in,
                              void* d_out, int out_size)
{
    const float* x2d   = (const float*)d_in[0];   // (64, 480, 640) f32
    const int*   ppix  = (const int*)  d_in[1];   // (N, 2) i32
    const int*   scale = (const int*)  d_in[2];   // scalar i32
    const int*   mask  = (const int*)  d_in[3];   // (N,) i32
    const float* pz    = (const float*)d_in[4];   // (N,) f32
    const float* depth = (const float*)d_in[5];   // (1, 480, 640) f32
    float* out = (float*)d_out;

    k_transpose<<<(int)(HWSZ / 64), 256>>>(x2d);

    k_fuse<<<(int)(NV / TILE), 512>>>(ppix, scale, mask, pz, depth, out);
}

// round 17
// speedup vs baseline: 1.1352x; 1.1352x over previous
#include <cuda_runtime.h>
#include <cuda_fp16.h>
#include <cuda_bf16.h>
#include <cstdint>

static constexpr int CCH = 64;
static constexpr int HH  = 480;
static constexpr int WW  = 640;
static constexpr long long HWSZ = (long long)HH * WW;   // 307200
static constexpr long long NV   = 256LL * 256 * 32;     // 2097152 voxels
static constexpr int TILE = 256;                        // voxels per block (2 halves)
static constexpr int HALF = 128;
static constexpr int PITCH_H = 66;                      // halves per smem row (132B)
static constexpr int PITCH_W = 33;                      // 32-bit words per row

// Scratch: transposed fp16 features, xTh[pixel * 64 + channel]  (39 MB, L2-resident)
__device__ __align__(16) __half g_xTh[(size_t)HWSZ * CCH];

// ---------------------------------------------------------------------------
// Transpose x2d (C, H*W) f32 -> xTh (H*W, C) f16.
// float4 streaming loads (read-once, keep L2 for xT), smem tile, half2 writes.
// ---------------------------------------------------------------------------
__global__ void __launch_bounds__(256) k_transpose(const float* __restrict__ x2d)
{
    __shared__ float tile[64][65];        // tile[channel][pixel]
    const int pbase = blockIdx.x * 64;
    const int tid  = threadIdx.x;
    const int c    = tid >> 2;            // 0..63 : channel
    const int q    = tid & 3;             // 0..3  : float4 quarter
    const int lane = tid & 31;
    const int w    = tid >> 5;            // 0..7

    const float4* src = reinterpret_cast<const float4*>(x2d + (long long)c * HWSZ + pbase);
#pragma unroll
    for (int it = 0; it < 4; it++) {
        const float4 v = __ldcs(src + q + it * 4);   // streaming: read-once
        const int p0 = (q + it * 4) * 4;
        tile[c][p0 + 0] = v.x;
        tile[c][p0 + 1] = v.y;
        tile[c][p0 + 2] = v.z;
        tile[c][p0 + 3] = v.w;
    }
    __syncthreads();

    __half2* xT2 = reinterpret_cast<__half2*>(g_xTh);
#pragma unroll
    for (int it = 0; it < 8; it++) {
        const int p  = it * 8 + w;
        const int c2 = lane * 2;
        const __half2 h = __floats2half2_rn(tile[c2][p], tile[c2 + 1][p]);
        xT2[(long long)(pbase + p) * 32 + lane] = h;
    }
}

__device__ __forceinline__ void sts_row(uint32_t* su, int v, int kk, const uint4& r)
{
    const int wbase = v * PITCH_W + 4 * kk;   // scalar STS.32 x4: conflict-free
    su[wbase + 0] = r.x;
    su[wbase + 1] = r.y;
    su[wbase + 2] = r.z;
    su[wbase + 3] = r.w;
}

// ---------------------------------------------------------------------------
// Fused kernel (512 threads, occ ~97%), 2-half pipeline:
//   A; bar; Bload(0); Bstore(0); bar; Bload(1); C(0); Bstore(1); bar; C(1)
// Half-1 gather latency hides under half-0's store phase.
// Output stores: __stcs (evict-first write-back; L2 write-combines the
// stream — measured optimum; __stwt regressed).
// ---------------------------------------------------------------------------
__global__ void __launch_bounds__(512) k_fuse(
    const int*   __restrict__ ppix,     // (N, 2) int32 : x, y
    const int*   __restrict__ scale_p,  // scalar int32
    const int*   __restrict__ mask,     // (N,) int32 (bool)
    const float* __restrict__ pz,       // (N,) float32
    const float* __restrict__ depth,    // (H*W,) float32
    float*       __restrict__ out)      // (64, N) float32
{
    __shared__ __align__(16) __half sm16[TILE][PITCH_H];  // 2 halves of 128 rows
    __shared__ float sm_w[TILE];
    __shared__ int   sm_fidx[TILE];

    uint32_t* su = reinterpret_cast<uint32_t*>(&sm16[0][0]);
    const int tid = threadIdx.x;
    const long long vbase = (long long)blockIdx.x * TILE;

    // ---- Phase A: indices + weights (threads 0..255, one voxel each) ----
    if (tid < TILE) {
        const long long i = vbase + tid;
        const int2 p = __ldcs(reinterpret_cast<const int2*>(ppix) + i);  // read-once
        const int  m = __ldcs(mask + i);
        const float z = __ldcs(pz + i);
        const int scale = scale_p[0];
        const int di = p.y * WW + p.x;
        const int fi = (scale == 1) ? di : ((p.y / scale) * WW + (p.x / scale));
        sm_fidx[tid] = fi;
        const float dv = m ? __ldg(depth + di) : 0.0f;
        const float d  = z - dv;
        const float gw = __expf(-0.5f * d * d);   // sigma = 1
        sm_w[tid] = m ? ((dv == 0.0f) ? 1.0f : gw) : 0.0f;
    }
    __syncthreads();

    // Gather lane mapping: 8 lanes per 128B fp16 voxel row.
    const int vt = tid >> 3;        // 0..63: voxel slot within pass
    const int kk = tid & 7;         // 0..7 : 16B chunk within row

    uint4 r0, r1;

    // ---- B_load(0) + B_store(0): rows 0..127 ----
    {
        const int va = vt;
        const int vb = 64 + vt;
        r0 = make_uint4(0u, 0u, 0u, 0u);
        r1 = make_uint4(0u, 0u, 0u, 0u);
        if (sm_w[va] != 0.0f)
            r0 = __ldg(reinterpret_cast<const uint4*>(g_xTh + (long long)sm_fidx[va] * CCH) + kk);
        if (sm_w[vb] != 0.0f)
            r1 = __ldg(reinterpret_cast<const uint4*>(g_xTh + (long long)sm_fidx[vb] * CCH) + kk);
        sts_row(su, va, kk, r0);
        sts_row(su, vb, kk, r1);
    }
    __syncthreads();

    // ---- B_load(1): rows 128..255 (latency overlapped with C(0)) ----
    {
        const int va = HALF + vt;
        const int vb = HALF + 64 + vt;
        r0 = make_uint4(0u, 0u, 0u, 0u);
        r1 = make_uint4(0u, 0u, 0u, 0u);
        if (sm_w[va] != 0.0f)
            r0 = __ldg(reinterpret_cast<const uint4*>(g_xTh + (long long)sm_fidx[va] * CCH) + kk);
        if (sm_w[vb] != 0.0f)
            r1 = __ldg(reinterpret_cast<const uint4*>(g_xTh + (long long)sm_fidx[vb] * CCH) + kk);
    }

    // ---- C(0): store half 0 while half-1 gather is in flight ----
    {
        const int vv = tid & (HALF - 1);       // 0..127
        const int cq = tid >> 7;               // 0..3: 16-channel quarter
        const float wv = sm_w[vv];
        float* op = out + vbase + vv;
        const int wrow = vv * PITCH_W;
#pragma unroll
        for (int it = 0; it < 8; it++) {
            const int c = cq * 16 + it * 2;
            const uint32_t bits = su[wrow + (c >> 1)];
            const float2 f = __half22float2(*reinterpret_cast<const __half2*>(&bits));
            __stcs(op + (long long)c * NV,       f.x * wv);
            __stcs(op + (long long)(c + 1) * NV, f.y * wv);
        }
    }

    // ---- B_store(1) ----
    sts_row(su, HALF + vt, kk, r0);
    sts_row(su, HALF + 64 + vt, kk, r1);
    __syncthreads();

    // ---- C(1): store half 1 ----
    {
        const int vv = tid & (HALF - 1);
        const int cq = tid >> 7;
        const int row = HALF + vv;
        const float wv = sm_w[row];
        float* op = out + vbase + row;
        const int wrow = row * PITCH_W;
#pragma unroll
        for (int it = 0; it < 8; it++) {
            const int c = cq * 16 + it * 2;
            const uint32_t bits = su[wrow + (c >> 1)];
            const float2 f = __half22float2(*reinterpret_cast<const __half2*>(&bits));
            __stcs(op + (long long)c * NV,       f.x * wv);
            __stcs(op + (long long)(c + 1) * NV, f.y * wv);
        }
    }
}

extern "C" void kernel_launch(void* const* d_in, const int* in_sizes, int n_in,
                              void* d_out, int out_size)
{
    const float* x2d   = (const float*)d_in[0];   // (64, 480, 640) f32
    const int*   ppix  = (const int*)  d_in[1];   // (N, 2) i32
    const int*   scale = (const int*)  d_in[2];   // scalar i32
    const int*   mask  = (const int*)  d_in[3];   // (N,) i32
    const float* pz    = (const float*)d_in[4];   // (N,) f32
    const float* depth = (const float*)d_in[5];   // (1, 480, 640) f32
    float* out = (float*)d_out;

    k_transpose<<<(int)(HWSZ / 64), 256>>>(x2d);

    k_fuse<<<(int)(NV / TILE), 512>>>(ppix, scale, mask, pz, depth, out);
}